// round 15
// baseline (speedup 1.0000x reference)
#include <cuda_runtime.h>
#include <cuda_bf16.h>
#include <cstdint>
#include <cstddef>

#define H 128
#define NTYPE 10
#define NREL 26
#define DEG_TOTAL 1828000
#define EDGE_TOTAL (26 * 300000)
#define BUF0_ROWS 414000
#define BUF1_ROWS 50000
#define TMP_ROWS 600000
#define AGG_ROWS 300000

// ---------------- scratch ----------------
__device__ float g_buf0[(size_t)BUF0_ROWS * H];
__device__ float g_buf1[(size_t)BUF1_ROWS * H];
__device__ float g_agg[(size_t)AGG_ROWS * H];     // bf16 hi/lo plane arena for dst-side
__device__ float g_tmp[(size_t)TMP_ROWS * H];
__device__ int   g_head[DEG_TOTAL];
__device__ int   g_next[EDGE_TOTAL];
__device__ float g_wsum[2 * NTYPE * H * H];
__device__ float g_bsum[2 * NTYPE * H];
// fragment-ordered weights: per matrix 4096 uint4 = [plane][np8][ks8][lane32]
__device__ __nv_bfloat16 g_wbf[72 * 2 * H * H];

__constant__ int c_rel_dst[NREL] = {1,0,2,0,3,0,4,0,5,0,6,0,7,6,6,5,7,5,5,4,3,4,8,2,9,2};

// ---------------- job descriptors ----------------
// GJob flags: 1=accumulate(red), 2=relu on A load, 4=A is pre-split bf16 planes
struct GJob { const float* A; const __nv_bfloat16* Wb; const float* bias; float* C;
              int M; int tile_base; int flags; int _pad; };
struct GBatch { GJob j[20]; int nj; };

// SJob flags: 1=relu on x, 2=red-accumulate fp32 out, 4=write pre-split bf16 planes
struct SJob { const float* x; const int* srcI; const int* head; const int* next;
              float* out; int n; int node_base; int flags; };
struct SBatch { SJob j[14]; int nj; };

struct CJob { const int* dstI; int* head; int* next; int E; int ebase; int _pad; };
struct CBatch { CJob j[22]; int nj; };

// ---------------- helpers ----------------
__device__ __forceinline__ uint32_t smem_to_u32(const void* p) {
    uint32_t a;
    asm("{ .reg .u64 t; cvta.to.shared.u64 t, %1; cvt.u32.u64 %0, t; }" : "=r"(a) : "l"(p));
    return a;
}

__device__ __forceinline__ void cvt8(const float* v, uint4& hi, uint4& lo) {
    uint32_t h[4], l[4];
    #pragma unroll
    for (int p = 0; p < 4; p++) {
        float a = v[2*p], b = v[2*p+1];
        __nv_bfloat16 ah = __float2bfloat16(a), bh = __float2bfloat16(b);
        float ar = a - __bfloat162float(ah), br = b - __bfloat162float(bh);
        __nv_bfloat16 al = __float2bfloat16(ar), bl2 = __float2bfloat16(br);
        h[p] = (uint32_t)__bfloat16_as_ushort(ah) | ((uint32_t)__bfloat16_as_ushort(bh) << 16);
        l[p] = (uint32_t)__bfloat16_as_ushort(al) | ((uint32_t)__bfloat16_as_ushort(bl2) << 16);
    }
    hi = make_uint4(h[0], h[1], h[2], h[3]);
    lo = make_uint4(l[0], l[1], l[2], l[3]);
}

#define LDMATRIX_X4(r0, r1, r2, r3, addr) \
    asm volatile("ldmatrix.sync.aligned.m8n8.x4.shared.b16 {%0,%1,%2,%3}, [%4];" \
                 : "=r"(r0), "=r"(r1), "=r"(r2), "=r"(r3) : "r"(addr))

#define MMA_BF16(c0, c1, c2, c3, a0, a1, a2, a3, b0, b1) \
    asm volatile("mma.sync.aligned.m16n8k16.row.col.f32.bf16.bf16.f32 " \
                 "{%0,%1,%2,%3}, {%4,%5,%6,%7}, {%8,%9}, {%0,%1,%2,%3};" \
                 : "+f"(c0), "+f"(c1), "+f"(c2), "+f"(c3) \
                 : "r"(a0), "r"(a1), "r"(a2), "r"(a3), "r"(b0), "r"(b1))

// ---------------- batched bf16 HMMA GEMM: 128x128 tile, 256 thr (8 warps, 32x64/warp) -
#define A_LD 136
#define SM_AH 0
#define SM_AL 34816
#define SM_BYTES 69632

__global__ void __launch_bounds__(256, 2) gemm_batched(GBatch bat)
{
    extern __shared__ char smem[];
    const uint32_t sb = smem_to_u32(smem);
    const int tid = threadIdx.x, lane = tid & 31, wid = tid >> 5;

    int jb = 0;
    while (jb + 1 < bat.nj && (int)blockIdx.x >= bat.j[jb + 1].tile_base) jb++;
    const GJob& J = bat.j[jb];
    const int m0 = (blockIdx.x - J.tile_base) * 128;
    const int M = J.M;
    const int accumulate = J.flags & 1;
    const int doRelu = J.flags & 2;
    const int presplit = J.flags & 4;
    const float* bias = J.bias;
    float* C = J.C;

    // ---- stage A (128 rows) ----
    if (presplit) {
        const uint4* srcH = (const uint4*)J.A + (size_t)m0 * 16;
        const uint4* srcL = (const uint4*)((const __nv_bfloat16*)J.A + (size_t)M * H) + (size_t)m0 * 16;
        #pragma unroll
        for (int it = 0; it < 8; it++) {
            int idx = tid + it * 256;              // 2048 uint4 per plane
            int n = idx >> 4, q = idx & 15;
            *(uint4*)(smem + SM_AH + (size_t)n * (A_LD * 2) + q * 16) = srcH[idx];
            *(uint4*)(smem + SM_AL + (size_t)n * (A_LD * 2) + q * 16) = srcL[idx];
        }
    } else {
        const int r = tid >> 1;                    // 0..127
        const int co = (tid & 1) * 64;
        const int m = m0 + r;
        if (m < M) {
            const float4* Ar = (const float4*)(J.A + (size_t)m * H);
            #pragma unroll
            for (int c = 0; c < 64; c += 8) {
                float4 f0 = Ar[(co + c) >> 2], f1 = Ar[((co + c) >> 2) + 1];
                float v[8] = {f0.x,f0.y,f0.z,f0.w,f1.x,f1.y,f1.z,f1.w};
                if (doRelu) {
                    #pragma unroll
                    for (int j = 0; j < 8; j++) v[j] = fmaxf(v[j], 0.f);
                }
                uint4 hi, lo;
                cvt8(v, hi, lo);
                *(uint4*)(smem + SM_AH + (size_t)(r * A_LD + co + c) * 2) = hi;
                *(uint4*)(smem + SM_AL + (size_t)(r * A_LD + co + c) * 2) = lo;
            }
        } else {
            uint4 z = make_uint4(0,0,0,0);
            #pragma unroll
            for (int c = 0; c < 64; c += 8) {
                *(uint4*)(smem + SM_AH + (size_t)(r * A_LD + co + c) * 2) = z;
                *(uint4*)(smem + SM_AL + (size_t)(r * A_LD + co + c) * 2) = z;
            }
        }
    }
    __syncthreads();

    // ---- warp tiling: 4x2 warps, each 32(m) x 64(n) ----
    const int warp_m = (wid >> 1) * 32;
    const int warp_n = (wid & 1) * 64;
    const int npg = warp_n >> 4;                   // 0 or 4

    float acc[2][8][4];
    #pragma unroll
    for (int mt = 0; mt < 2; mt++)
        #pragma unroll
        for (int nt = 0; nt < 8; nt++)
            #pragma unroll
            for (int q = 0; q < 4; q++) acc[mt][nt][q] = 0.0f;

    const int lrow = lane & 15;
    const int lcol = (lane >> 4) << 3;

    uint32_t aoff[2];
    #pragma unroll
    for (int mt = 0; mt < 2; mt++)
        aoff[mt] = (uint32_t)(((warp_m + mt * 16 + lrow) * A_LD + lcol) * 2);

    // fragment-ordered B: offset = ((plane*8 + np)*8 + ks)*32 + lane  (uint4 units)
    const uint4* __restrict__ WbF = (const uint4*)J.Wb;

    #pragma unroll
    for (int ks = 0; ks < 8; ks++) {
        const uint32_t kb = ks * 32;
        uint4 bh[4], bl[4];
        #pragma unroll
        for (int np = 0; np < 4; np++) {
            bh[np] = __ldg(WbF + (((0 + npg + np) * 8 + ks) * 32 + lane));
            bl[np] = __ldg(WbF + (((8 + npg + np) * 8 + ks) * 32 + lane));
        }
        uint32_t ah[2][4], al[2][4];
        #pragma unroll
        for (int mt = 0; mt < 2; mt++) {
            LDMATRIX_X4(ah[mt][0], ah[mt][1], ah[mt][2], ah[mt][3], sb + SM_AH + aoff[mt] + kb);
            LDMATRIX_X4(al[mt][0], al[mt][1], al[mt][2], al[mt][3], sb + SM_AL + aoff[mt] + kb);
        }
        #pragma unroll
        for (int mt = 0; mt < 2; mt++) {
            #pragma unroll
            for (int np = 0; np < 4; np++) {
                const int n0 = np * 2, n1 = np * 2 + 1;
                // hh
                MMA_BF16(acc[mt][n0][0], acc[mt][n0][1], acc[mt][n0][2], acc[mt][n0][3],
                         ah[mt][0], ah[mt][1], ah[mt][2], ah[mt][3], bh[np].x, bh[np].z);
                MMA_BF16(acc[mt][n1][0], acc[mt][n1][1], acc[mt][n1][2], acc[mt][n1][3],
                         ah[mt][0], ah[mt][1], ah[mt][2], ah[mt][3], bh[np].y, bh[np].w);
                // lh
                MMA_BF16(acc[mt][n0][0], acc[mt][n0][1], acc[mt][n0][2], acc[mt][n0][3],
                         al[mt][0], al[mt][1], al[mt][2], al[mt][3], bh[np].x, bh[np].z);
                MMA_BF16(acc[mt][n1][0], acc[mt][n1][1], acc[mt][n1][2], acc[mt][n1][3],
                         al[mt][0], al[mt][1], al[mt][2], al[mt][3], bh[np].y, bh[np].w);
                // hl
                MMA_BF16(acc[mt][n0][0], acc[mt][n0][1], acc[mt][n0][2], acc[mt][n0][3],
                         ah[mt][0], ah[mt][1], ah[mt][2], ah[mt][3], bl[np].x, bl[np].z);
                MMA_BF16(acc[mt][n1][0], acc[mt][n1][1], acc[mt][n1][2], acc[mt][n1][3],
                         ah[mt][0], ah[mt][1], ah[mt][2], ah[mt][3], bl[np].y, bl[np].w);
            }
        }
    }

    // ---- epilogue ----
    const int qrow = lane >> 2;
    const int qcol = (lane & 3) * 2;
    #pragma unroll
    for (int mt = 0; mt < 2; mt++) {
        #pragma unroll
        for (int half = 0; half < 2; half++) {
            const int m = m0 + warp_m + mt * 16 + qrow + half * 8;
            if (m < M) {
                float* cp = C + (size_t)m * H;
                #pragma unroll
                for (int nt = 0; nt < 8; nt++) {
                    const int c = warp_n + nt * 8 + qcol;
                    float v0 = acc[mt][nt][half * 2 + 0];
                    float v1 = acc[mt][nt][half * 2 + 1];
                    if (accumulate) {
                        asm volatile("red.global.add.v2.f32 [%0], {%1,%2};"
                                     :: "l"(cp + c), "f"(v0), "f"(v1) : "memory");
                    } else {
                        if (bias) { v0 += bias[c]; v1 += bias[c + 1]; }
                        *(float2*)(cp + c) = make_float2(v0, v1);
                    }
                }
            }
        }
    }
}

// ---------------- Wr / bias reduction ----------------
__global__ void __launch_bounds__(256) wsum_kernel(
    const float* __restrict__ Wr, const float* __restrict__ bl,
    float* __restrict__ wsum, float* __restrict__ bsum)
{
    int layer = blockIdx.x / NTYPE;
    int t = blockIdx.x % NTYPE;
    const float* base = Wr + (size_t)layer * NREL * H * H;
    float* outw = wsum + ((size_t)layer * NTYPE + t) * H * H;
    for (int e = threadIdx.x; e < H * H; e += 256) {
        float a = 0.f;
        #pragma unroll
        for (int r = 0; r < NREL; r++)
            if (c_rel_dst[r] == t) a += base[(size_t)r * H * H + e];
        outw[e] = a;
    }
    if (threadIdx.x < H) {
        float a = 0.f;
        #pragma unroll
        for (int r = 0; r < NREL; r++)
            if (c_rel_dst[r] == t) a += bl[((size_t)layer * NREL + r) * H + threadIdx.x];
        bsum[((size_t)layer * NTYPE + t) * H + threadIdx.x] = a;
    }
}

// ---------------- weight conversion: fp32 [k][n] -> fragment-ordered bf16 hi/lo ------
__global__ void __launch_bounds__(256) wcvt_kernel(
    const float* __restrict__ wsum, const float* __restrict__ Wl,
    __nv_bfloat16* __restrict__ wbf)
{
    int m = blockIdx.x;   // 0..71
    const float* src = (m < 20) ? (wsum + (size_t)m * H * H)
                                : (Wl + (size_t)(m - 20) * H * H);
    uint4* dst = (uint4*)(wbf + (size_t)m * 2 * H * H);
    for (int idx = threadIdx.x; idx < 4096; idx += 256) {
        int plane = idx >> 11;
        int npg = (idx >> 8) & 7;
        int ks = (idx >> 5) & 7;
        int lane = idx & 31;
        uint32_t r[4];
        #pragma unroll
        for (int j = 0; j < 4; j++) {
            int row_n = npg * 16 + (j & 1) * 8 + (lane >> 2);
            int col_k = ks * 16 + (j >> 1) * 8 + 2 * (lane & 3);
            float w0 = src[col_k * H + row_n];
            float w1 = src[(col_k + 1) * H + row_n];
            __nv_bfloat16 h0 = __float2bfloat16(w0), h1 = __float2bfloat16(w1);
            if (plane == 0) {
                r[j] = (uint32_t)__bfloat16_as_ushort(h0)
                     | ((uint32_t)__bfloat16_as_ushort(h1) << 16);
            } else {
                float l0 = w0 - __bfloat162float(h0);
                float l1 = w1 - __bfloat162float(h1);
                r[j] = (uint32_t)__bfloat16_as_ushort(__float2bfloat16(l0))
                     | ((uint32_t)__bfloat16_as_ushort(__float2bfloat16(l1)) << 16);
            }
        }
        dst[idx] = make_uint4(r[0], r[1], r[2], r[3]);
    }
}

// ---------------- batched chain build ----------------
__global__ void __launch_bounds__(256) build_chain_batched(CBatch bat, int total)
{
    int g = blockIdx.x * blockDim.x + threadIdx.x;
    if (g >= total) return;
    int jb = 0;
    while (jb + 1 < bat.nj && g >= bat.j[jb + 1].ebase) jb++;
    const CJob& J = bat.j[jb];
    int e = g - J.ebase;
    J.next[e] = atomicExch(J.head + __ldg(J.dstI + e), e);
}

// ---------------- batched chain gather (R8-proven: 1 chain / warp) ----------------
__global__ void __launch_bounds__(256) gather_batched(SBatch bat, int total)
{
    int gw = blockIdx.x * (blockDim.x >> 5) + (threadIdx.x >> 5);
    if (gw >= total) return;
    int jb = 0;
    while (jb + 1 < bat.nj && gw >= bat.j[jb + 1].node_base) jb++;
    const SJob& J = bat.j[jb];
    const int node = gw - J.node_base;
    const int lane = threadIdx.x & 31;
    const int doRelu = J.flags & 1;
    const float* x = J.x;
    const int* srcI = J.srcI;
    const int* next = J.next;

    int e = __ldg(J.head + node);
    float4 acc = make_float4(0.f, 0.f, 0.f, 0.f);
    float cnt = 0.f;
    while (e >= 0) {
        int s  = __ldg(srcI + e);
        int nx = __ldg(next + e);
        float4 v = __ldg(((const float4*)(x + (size_t)s * H)) + lane);
        if (doRelu) {
            v.x = fmaxf(v.x, 0.f); v.y = fmaxf(v.y, 0.f);
            v.z = fmaxf(v.z, 0.f); v.w = fmaxf(v.w, 0.f);
        }
        acc.x += v.x; acc.y += v.y; acc.z += v.z; acc.w += v.w;
        cnt += 1.f;
        e = nx;
    }
    float sc = 1.0f / fmaxf(cnt, 1.0f);
    acc.x *= sc; acc.y *= sc; acc.z *= sc; acc.w *= sc;

    if (J.flags & 4) {
        float v[4] = {acc.x, acc.y, acc.z, acc.w};
        uint32_t h[2], l[2];
        #pragma unroll
        for (int p = 0; p < 2; p++) {
            float a = v[2*p], b = v[2*p+1];
            __nv_bfloat16 ah = __float2bfloat16(a), bh = __float2bfloat16(b);
            float ar = a - __bfloat162float(ah), br = b - __bfloat162float(bh);
            h[p] = (uint32_t)__bfloat16_as_ushort(ah) | ((uint32_t)__bfloat16_as_ushort(bh) << 16);
            l[p] = (uint32_t)__bfloat16_as_ushort(__float2bfloat16(ar))
                 | ((uint32_t)__bfloat16_as_ushort(__float2bfloat16(br)) << 16);
        }
        __nv_bfloat16* hi = (__nv_bfloat16*)J.out;
        *(uint2*)(hi + (size_t)node * H + lane * 4) = make_uint2(h[0], h[1]);
        *(uint2*)(hi + (size_t)J.n * H + (size_t)node * H + lane * 4) = make_uint2(l[0], l[1]);
    } else if (J.flags & 2) {
        float* p = J.out + (size_t)node * H + lane * 4;
        asm volatile("red.global.add.v4.f32 [%0], {%1,%2,%3,%4};"
                     :: "l"(p), "f"(acc.x), "f"(acc.y), "f"(acc.z), "f"(acc.w) : "memory");
    } else {
        *(float4*)(J.out + (size_t)node * H + lane * 4) = acc;
    }
}

// ---------------- final linear ----------------
__global__ void __launch_bounds__(128) final_kernel(
    const float* __restrict__ X, const float* __restrict__ W,
    const float* __restrict__ b, float* __restrict__ out, int M)
{
    __shared__ float Ws[H * 64];
    __shared__ float bs[64];
    for (int i = threadIdx.x; i < H * 64; i += 128) Ws[i] = W[i];
    if (threadIdx.x < 64) bs[threadIdx.x] = b[threadIdx.x];
    __syncthreads();
    int m = blockIdx.x * 128 + threadIdx.x;
    if (m >= M) return;
    float acc[64];
    #pragma unroll
    for (int j = 0; j < 64; j++) acc[j] = bs[j];
    const float* x = X + (size_t)m * H;
    for (int k = 0; k < H; k++) {
        float xv = fmaxf(x[k], 0.f);
        #pragma unroll
        for (int j = 0; j < 64; j++) acc[j] += xv * Ws[k * 64 + j];
    }
    float* o = out + (size_t)m * 64;
    #pragma unroll
    for (int j = 0; j < 64; j++) o[j] = acc[j];
}

// ---------------- host ----------------
static const int NN[NTYPE]   = {50000,2000,80000,10000,2000,150000,120000,100000,60000,40000};
static const int OFFS[NTYPE] = {0,50000,52000,132000,142000,144000,294000,414000,514000,574000};
static const int R_SRC[NREL] = {0,1,0,2,0,3,0,4,0,5,0,6,6,7,5,6,5,7,4,5,4,3,2,8,2,9};
static const int R_DST[NREL] = {1,0,2,0,3,0,4,0,5,0,6,0,7,6,6,5,7,5,5,4,3,4,8,2,9,2};
static const int R_EI[NREL]  = {10,10,11,11,12,12,13,13,14,14,15,15,16,16,17,17,18,18,19,19,20,20,21,21,22,22};
static const int R_FLIP[NREL]= {0,1,0,1,0,1,0,1,0,1,0,1,0,1,0,1,0,1,0,1,0,1,0,1,0,1};

static inline int l1_type_needed(int t) { return t < 7; }
static inline int l1_rel_needed(int r)  { return R_DST[r] < 7; }
static inline int l2_rel_needed(int r)  { return R_DST[r] == 0; }

// one-time stream/event setup (host-side only; no device memory)
static cudaStream_t g_s1 = nullptr;
static cudaEvent_t g_evF = nullptr, g_evJ = nullptr;

extern "C" void kernel_launch(void* const* d_in, const int* in_sizes, int n_in,
                              void* d_out, int out_size)
{
    if (!g_s1) {
        cudaStreamCreate(&g_s1);
        cudaEventCreateWithFlags(&g_evF, cudaEventDisableTiming);
        cudaEventCreateWithFlags(&g_evJ, cudaEventDisableTiming);
    }

    const float* Wl   = (const float*)d_in[23];
    const float* bl   = (const float*)d_in[24];
    const float* Wr   = (const float*)d_in[25];
    const float* linW = (const float*)d_in[26];
    const float* linb = (const float*)d_in[27];

    float *buf0, *buf1, *agg, *tmp, *wsum, *bsum;
    int *head, *nxt;
    __nv_bfloat16* wbf;
    cudaGetSymbolAddress((void**)&buf0, g_buf0);
    cudaGetSymbolAddress((void**)&buf1, g_buf1);
    cudaGetSymbolAddress((void**)&agg,  g_agg);
    cudaGetSymbolAddress((void**)&tmp,  g_tmp);
    cudaGetSymbolAddress((void**)&head, g_head);
    cudaGetSymbolAddress((void**)&nxt,  g_next);
    cudaGetSymbolAddress((void**)&wsum, g_wsum);
    cudaGetSymbolAddress((void**)&bsum, g_bsum);
    cudaGetSymbolAddress((void**)&wbf,  g_wbf);

    cudaFuncSetAttribute(gemm_batched, cudaFuncAttributeMaxDynamicSharedMemorySize, SM_BYTES);

    int DEGOFF[NREL], EOFF[NREL];
    {
        int a = 0, b2 = 0;
        for (int r = 0; r < NREL; r++) {
            DEGOFF[r] = a; a += NN[R_DST[r]];
            EOFF[r] = b2; b2 += in_sizes[R_EI[r]] / 2;
        }
    }

    // ---- prep: fork — weights on s0, chains on s1 ----
    cudaEventRecord(g_evF, 0);
    cudaStreamWaitEvent(g_s1, g_evF, 0);

    wsum_kernel<<<2 * NTYPE, 256>>>(Wr, bl, wsum, bsum);
    wcvt_kernel<<<72, 256>>>(wsum, Wl, wbf);

    cudaMemsetAsync(head, 0xFF, (size_t)DEG_TOTAL * sizeof(int), g_s1);
    {
        CBatch cb; cb.nj = 0;
        int etot = 0;
        for (int r = 0; r < NREL; r++) {
            if (!l1_rel_needed(r) && !l2_rel_needed(r)) continue;
            int ii = R_EI[r];
            const int* ei = (const int*)d_in[ii];
            int E = in_sizes[ii] / 2;
            const int* dstI = R_FLIP[r] ? ei : ei + E;
            CJob& J = cb.j[cb.nj++];
            J.dstI = dstI; J.head = head + DEGOFF[r]; J.next = nxt + EOFF[r];
            J.E = E; J.ebase = etot;
            etot += E;
        }
        build_chain_batched<<<(etot + 255) / 256, 256, 0, g_s1>>>(cb, etot);
    }
    cudaEventRecord(g_evJ, g_s1);
    cudaStreamWaitEvent(0, g_evJ, 0);

    const float* cur[NTYPE];
    for (int t = 0; t < NTYPE; t++) cur[t] = (const float*)d_in[t];
    float* bufs[2] = {buf0, buf1};

    for (int layer = 0; layer < 2; layer++) {
        float* outbuf = bufs[layer];
        const int lrelu = (layer == 1);
        const int aflags = lrelu ? 2 : 0;

        GBatch ga; ga.nj = 0; int gaTiles = 0;   // phase A GEMMs (s0)
        SBatch sd; sd.nj = 0; int sdNodes = 0;   // phase A gathers (s1): dst-side presplit
        GBatch gb; gb.nj = 0; int gbTiles = 0;   // phase B GEMMs (s0)
        SBatch ss; ss.nj = 0; int ssNodes = 0;   // phase B gathers (s1): src-side red
        size_t tmpoff = 0, aggoff = 0;

        // self terms -> phase A
        for (int t = 0; t < NTYPE; t++) {
            if (layer == 0 ? !l1_type_needed(t) : (t != 0)) continue;
            int outoff = (layer == 0) ? OFFS[t] : 0;
            GJob& J = ga.j[ga.nj++];
            J.A = cur[t];
            J.Wb = wbf + (size_t)(layer * NTYPE + t) * 2 * H * H;
            J.bias = bsum + ((size_t)layer * NTYPE + t) * H;
            J.C = outbuf + (size_t)outoff * H;
            J.M = NN[t]; J.tile_base = gaTiles; J.flags = aflags;
            gaTiles += (NN[t] + 127) / 128;
        }

        // neighbor terms
        for (int r = 0; r < NREL; r++) {
            if (layer == 0 ? !l1_rel_needed(r) : !l2_rel_needed(r)) continue;
            int s = R_SRC[r], d = R_DST[r], ii = R_EI[r];
            const int* ei = (const int*)d_in[ii];
            int E = in_sizes[ii] / 2;
            const int* srcI = R_FLIP[r] ? ei + E : ei;
            int nd = NN[d];
            int outoff = (layer == 0) ? OFFS[d] : 0;
            const __nv_bfloat16* wmat = wbf + (size_t)(20 + layer * NREL + r) * 2 * H * H;

            if (NN[s] < nd) {
                // src-side: GEMM into tmp (phase A, s0), gather-red into out (phase B, s1)
                float* tp = tmp + tmpoff * H;
                tmpoff += NN[s];
                GJob& J = ga.j[ga.nj++];
                J.A = cur[s]; J.Wb = wmat; J.bias = nullptr; J.C = tp;
                J.M = NN[s]; J.tile_base = gaTiles; J.flags = aflags;
                gaTiles += (NN[s] + 127) / 128;

                SJob& S = ss.j[ss.nj++];
                S.x = tp; S.srcI = srcI; S.head = head + DEGOFF[r]; S.next = nxt + EOFF[r];
                S.out = outbuf + (size_t)outoff * H; S.n = nd;
                S.node_base = ssNodes; S.flags = 2;
                ssNodes += nd;
            } else {
                // dst-side: gather mean -> presplit planes (phase A, s1), GEMM-red (phase B, s0)
                float* ap = agg + aggoff * H;
                aggoff += nd;
                SJob& S = sd.j[sd.nj++];
                S.x = cur[s]; S.srcI = srcI; S.head = head + DEGOFF[r]; S.next = nxt + EOFF[r];
                S.out = ap; S.n = nd;
                S.node_base = sdNodes; S.flags = (lrelu ? 1 : 0) | 4;
                sdNodes += nd;

                GJob& J = gb.j[gb.nj++];
                J.A = ap; J.Wb = wmat; J.bias = nullptr;
                J.C = outbuf + (size_t)outoff * H;
                J.M = nd; J.tile_base = gbTiles; J.flags = 1 | 4;
                gbTiles += (nd + 127) / 128;
            }
        }

        // ---- Phase A: ga (s0) || sd (s1) ----
        cudaEventRecord(g_evF, 0);
        cudaStreamWaitEvent(g_s1, g_evF, 0);
        gemm_batched<<<gaTiles, 256, SM_BYTES>>>(ga);
        gather_batched<<<(sdNodes + 7) / 8, 256, 0, g_s1>>>(sd, sdNodes);
        cudaEventRecord(g_evJ, g_s1);
        cudaStreamWaitEvent(0, g_evJ, 0);

        // ---- Phase B: gb (s0) || ss (s1) ----
        cudaEventRecord(g_evF, 0);
        cudaStreamWaitEvent(g_s1, g_evF, 0);
        gemm_batched<<<gbTiles, 256, SM_BYTES>>>(gb);
        gather_batched<<<(ssNodes + 7) / 8, 256, 0, g_s1>>>(ss, ssNodes);
        cudaEventRecord(g_evJ, g_s1);
        cudaStreamWaitEvent(0, g_evJ, 0);

        if (layer == 0)
            for (int t = 0; t < 7; t++) cur[t] = buf0 + (size_t)OFFS[t] * H;
    }

    final_kernel<<<(BUF1_ROWS + 127) / 128, 128>>>(buf1, linW, linb, (float*)d_out, BUF1_ROWS);
}

// round 16
// speedup vs baseline: 1.0361x; 1.0361x over previous
#include <cuda_runtime.h>
#include <cuda_bf16.h>
#include <cstdint>
#include <cstddef>

#define H 128
#define NTYPE 10
#define NREL 26
#define DEG_TOTAL 1828000
#define EDGE_TOTAL (26 * 300000)
#define BUF0_ROWS 414000
#define BUF1_ROWS 50000
#define TMP_ROWS 600000
#define AGG_ROWS 700000

// ---------------- scratch ----------------
__device__ float g_buf0[(size_t)BUF0_ROWS * H];
__device__ float g_buf1[(size_t)BUF1_ROWS * H];
__device__ float g_agg[(size_t)AGG_ROWS * H];     // bf16 hi/lo plane arena for dst-side
__device__ float g_tmp[(size_t)TMP_ROWS * H];
__device__ int   g_head[DEG_TOTAL];
__device__ int   g_next[EDGE_TOTAL];
__device__ float g_wsum[2 * NTYPE * H * H];
__device__ float g_bsum[2 * NTYPE * H];
// fragment-ordered weights: per matrix 4096 uint4 = [plane][np8][ks8][lane32]
__device__ __nv_bfloat16 g_wbf[72 * 2 * H * H];

__constant__ int c_rel_dst[NREL] = {1,0,2,0,3,0,4,0,5,0,6,0,7,6,6,5,7,5,5,4,3,4,8,2,9,2};

// ---------------- job descriptors ----------------
// GJob flags: 1=accumulate(red), 2=relu on A load, 4=A is pre-split bf16 planes
struct GJob { const float* A; const __nv_bfloat16* Wb; const float* bias; float* C;
              int M; int tile_base; int flags; int _pad; };
struct GBatch { GJob j[20]; int nj; };

// SJob flags: 1=relu on x, 2=red-accumulate fp32 out, 4=write pre-split bf16 planes
struct SJob { const float* x; const int* srcI; const int* head; const int* next;
              float* out; int n; int node_base; int flags; };
struct SBatch { SJob j[14]; int nj; };

struct CJob { const int* dstI; int* head; int* next; int E; int ebase; int _pad; };
struct CBatch { CJob j[22]; int nj; };

// ---------------- helpers ----------------
__device__ __forceinline__ uint32_t smem_to_u32(const void* p) {
    uint32_t a;
    asm("{ .reg .u64 t; cvta.to.shared.u64 t, %1; cvt.u32.u64 %0, t; }" : "=r"(a) : "l"(p));
    return a;
}

__device__ __forceinline__ void cvt8(const float* v, uint4& hi, uint4& lo) {
    uint32_t h[4], l[4];
    #pragma unroll
    for (int p = 0; p < 4; p++) {
        float a = v[2*p], b = v[2*p+1];
        __nv_bfloat16 ah = __float2bfloat16(a), bh = __float2bfloat16(b);
        float ar = a - __bfloat162float(ah), br = b - __bfloat162float(bh);
        __nv_bfloat16 al = __float2bfloat16(ar), bl2 = __float2bfloat16(br);
        h[p] = (uint32_t)__bfloat16_as_ushort(ah) | ((uint32_t)__bfloat16_as_ushort(bh) << 16);
        l[p] = (uint32_t)__bfloat16_as_ushort(al) | ((uint32_t)__bfloat16_as_ushort(bl2) << 16);
    }
    hi = make_uint4(h[0], h[1], h[2], h[3]);
    lo = make_uint4(l[0], l[1], l[2], l[3]);
}

#define LDMATRIX_X4(r0, r1, r2, r3, addr) \
    asm volatile("ldmatrix.sync.aligned.m8n8.x4.shared.b16 {%0,%1,%2,%3}, [%4];" \
                 : "=r"(r0), "=r"(r1), "=r"(r2), "=r"(r3) : "r"(addr))

#define MMA_BF16(c0, c1, c2, c3, a0, a1, a2, a3, b0, b1) \
    asm volatile("mma.sync.aligned.m16n8k16.row.col.f32.bf16.bf16.f32 " \
                 "{%0,%1,%2,%3}, {%4,%5,%6,%7}, {%8,%9}, {%0,%1,%2,%3};" \
                 : "+f"(c0), "+f"(c1), "+f"(c2), "+f"(c3) \
                 : "r"(a0), "r"(a1), "r"(a2), "r"(a3), "r"(b0), "r"(b1))

// ---------------- batched bf16 HMMA GEMM: 64x128 tile, 128 thr (4 warps, 32x64/warp) --
#define A_LD 136
#define SM_AH 0
#define SM_AL 17408
#define SM_BYTES 34816

__global__ void __launch_bounds__(128, 4) gemm_batched(GBatch bat)
{
    extern __shared__ char smem[];
    const uint32_t sb = smem_to_u32(smem);
    const int tid = threadIdx.x, lane = tid & 31, wid = tid >> 5;

    int jb = 0;
    while (jb + 1 < bat.nj && (int)blockIdx.x >= bat.j[jb + 1].tile_base) jb++;
    const GJob& J = bat.j[jb];
    const int m0 = (blockIdx.x - J.tile_base) * 64;
    const int M = J.M;
    const int accumulate = J.flags & 1;
    const int doRelu = J.flags & 2;
    const int presplit = J.flags & 4;
    const float* bias = J.bias;
    float* C = J.C;

    // ---- stage A (64 rows) ----
    if (presplit) {
        const uint4* srcH = (const uint4*)J.A + (size_t)m0 * 16;
        const uint4* srcL = (const uint4*)((const __nv_bfloat16*)J.A + (size_t)M * H) + (size_t)m0 * 16;
        #pragma unroll
        for (int it = 0; it < 8; it++) {
            int idx = tid + it * 128;              // 1024 uint4 per plane
            int n = idx >> 4, q = idx & 15;
            *(uint4*)(smem + SM_AH + (size_t)n * (A_LD * 2) + q * 16) = srcH[idx];
            *(uint4*)(smem + SM_AL + (size_t)n * (A_LD * 2) + q * 16) = srcL[idx];
        }
    } else {
        const int r = tid >> 1;                    // 0..63
        const int co = (tid & 1) * 64;
        const int m = m0 + r;
        if (m < M) {
            const float4* Ar = (const float4*)(J.A + (size_t)m * H);
            #pragma unroll
            for (int c = 0; c < 64; c += 8) {
                float4 f0 = Ar[(co + c) >> 2], f1 = Ar[((co + c) >> 2) + 1];
                float v[8] = {f0.x,f0.y,f0.z,f0.w,f1.x,f1.y,f1.z,f1.w};
                if (doRelu) {
                    #pragma unroll
                    for (int j = 0; j < 8; j++) v[j] = fmaxf(v[j], 0.f);
                }
                uint4 hi, lo;
                cvt8(v, hi, lo);
                *(uint4*)(smem + SM_AH + (size_t)(r * A_LD + co + c) * 2) = hi;
                *(uint4*)(smem + SM_AL + (size_t)(r * A_LD + co + c) * 2) = lo;
            }
        } else {
            uint4 z = make_uint4(0,0,0,0);
            #pragma unroll
            for (int c = 0; c < 64; c += 8) {
                *(uint4*)(smem + SM_AH + (size_t)(r * A_LD + co + c) * 2) = z;
                *(uint4*)(smem + SM_AL + (size_t)(r * A_LD + co + c) * 2) = z;
            }
        }
    }
    __syncthreads();

    // ---- warp tiling: 2x2 warps, each 32(m) x 64(n) ----
    const int warp_m = (wid >> 1) * 32;
    const int warp_n = (wid & 1) * 64;
    const int npg = warp_n >> 4;                   // 0 or 4

    float acc[2][8][4];
    #pragma unroll
    for (int mt = 0; mt < 2; mt++)
        #pragma unroll
        for (int nt = 0; nt < 8; nt++)
            #pragma unroll
            for (int q = 0; q < 4; q++) acc[mt][nt][q] = 0.0f;

    const int lrow = lane & 15;
    const int lcol = (lane >> 4) << 3;

    uint32_t aoff[2];
    #pragma unroll
    for (int mt = 0; mt < 2; mt++)
        aoff[mt] = (uint32_t)(((warp_m + mt * 16 + lrow) * A_LD + lcol) * 2);

    // fragment-ordered B: offset = ((plane*8 + np)*8 + ks)*32 + lane  (uint4 units)
    const uint4* __restrict__ WbF = (const uint4*)J.Wb;

    #pragma unroll
    for (int ks = 0; ks < 8; ks++) {
        const uint32_t kb = ks * 32;
        uint4 bh[4], bl[4];
        #pragma unroll
        for (int np = 0; np < 4; np++) {
            bh[np] = __ldg(WbF + (((0 + npg + np) * 8 + ks) * 32 + lane));
            bl[np] = __ldg(WbF + (((8 + npg + np) * 8 + ks) * 32 + lane));
        }
        uint32_t ah[2][4], al[2][4];
        #pragma unroll
        for (int mt = 0; mt < 2; mt++) {
            LDMATRIX_X4(ah[mt][0], ah[mt][1], ah[mt][2], ah[mt][3], sb + SM_AH + aoff[mt] + kb);
            LDMATRIX_X4(al[mt][0], al[mt][1], al[mt][2], al[mt][3], sb + SM_AL + aoff[mt] + kb);
        }
        #pragma unroll
        for (int mt = 0; mt < 2; mt++) {
            #pragma unroll
            for (int np = 0; np < 4; np++) {
                const int n0 = np * 2, n1 = np * 2 + 1;
                // hh
                MMA_BF16(acc[mt][n0][0], acc[mt][n0][1], acc[mt][n0][2], acc[mt][n0][3],
                         ah[mt][0], ah[mt][1], ah[mt][2], ah[mt][3], bh[np].x, bh[np].z);
                MMA_BF16(acc[mt][n1][0], acc[mt][n1][1], acc[mt][n1][2], acc[mt][n1][3],
                         ah[mt][0], ah[mt][1], ah[mt][2], ah[mt][3], bh[np].y, bh[np].w);
                // lh
                MMA_BF16(acc[mt][n0][0], acc[mt][n0][1], acc[mt][n0][2], acc[mt][n0][3],
                         al[mt][0], al[mt][1], al[mt][2], al[mt][3], bh[np].x, bh[np].z);
                MMA_BF16(acc[mt][n1][0], acc[mt][n1][1], acc[mt][n1][2], acc[mt][n1][3],
                         al[mt][0], al[mt][1], al[mt][2], al[mt][3], bh[np].y, bh[np].w);
                // hl
                MMA_BF16(acc[mt][n0][0], acc[mt][n0][1], acc[mt][n0][2], acc[mt][n0][3],
                         ah[mt][0], ah[mt][1], ah[mt][2], ah[mt][3], bl[np].x, bl[np].z);
                MMA_BF16(acc[mt][n1][0], acc[mt][n1][1], acc[mt][n1][2], acc[mt][n1][3],
                         ah[mt][0], ah[mt][1], ah[mt][2], ah[mt][3], bl[np].y, bl[np].w);
            }
        }
    }

    // ---- epilogue ----
    const int qrow = lane >> 2;
    const int qcol = (lane & 3) * 2;
    #pragma unroll
    for (int mt = 0; mt < 2; mt++) {
        #pragma unroll
        for (int half = 0; half < 2; half++) {
            const int m = m0 + warp_m + mt * 16 + qrow + half * 8;
            if (m < M) {
                float* cp = C + (size_t)m * H;
                #pragma unroll
                for (int nt = 0; nt < 8; nt++) {
                    const int c = warp_n + nt * 8 + qcol;
                    float v0 = acc[mt][nt][half * 2 + 0];
                    float v1 = acc[mt][nt][half * 2 + 1];
                    if (accumulate) {
                        asm volatile("red.global.add.v2.f32 [%0], {%1,%2};"
                                     :: "l"(cp + c), "f"(v0), "f"(v1) : "memory");
                    } else {
                        if (bias) { v0 += bias[c]; v1 += bias[c + 1]; }
                        *(float2*)(cp + c) = make_float2(v0, v1);
                    }
                }
            }
        }
    }
}

// ---------------- Wr / bias reduction ----------------
__global__ void __launch_bounds__(256) wsum_kernel(
    const float* __restrict__ Wr, const float* __restrict__ bl,
    float* __restrict__ wsum, float* __restrict__ bsum)
{
    int layer = blockIdx.x / NTYPE;
    int t = blockIdx.x % NTYPE;
    const float* base = Wr + (size_t)layer * NREL * H * H;
    float* outw = wsum + ((size_t)layer * NTYPE + t) * H * H;
    for (int e = threadIdx.x; e < H * H; e += 256) {
        float a = 0.f;
        #pragma unroll
        for (int r = 0; r < NREL; r++)
            if (c_rel_dst[r] == t) a += base[(size_t)r * H * H + e];
        outw[e] = a;
    }
    if (threadIdx.x < H) {
        float a = 0.f;
        #pragma unroll
        for (int r = 0; r < NREL; r++)
            if (c_rel_dst[r] == t) a += bl[((size_t)layer * NREL + r) * H + threadIdx.x];
        bsum[((size_t)layer * NTYPE + t) * H + threadIdx.x] = a;
    }
}

// ---------------- weight conversion: fp32 [k][n] -> fragment-ordered bf16 hi/lo ------
__global__ void __launch_bounds__(256) wcvt_kernel(
    const float* __restrict__ wsum, const float* __restrict__ Wl,
    __nv_bfloat16* __restrict__ wbf)
{
    int m = blockIdx.x;   // 0..71
    const float* src = (m < 20) ? (wsum + (size_t)m * H * H)
                                : (Wl + (size_t)(m - 20) * H * H);
    uint4* dst = (uint4*)(wbf + (size_t)m * 2 * H * H);
    for (int idx = threadIdx.x; idx < 4096; idx += 256) {
        int plane = idx >> 11;
        int npg = (idx >> 8) & 7;
        int ks = (idx >> 5) & 7;
        int lane = idx & 31;
        uint32_t r[4];
        #pragma unroll
        for (int j = 0; j < 4; j++) {
            int row_n = npg * 16 + (j & 1) * 8 + (lane >> 2);
            int col_k = ks * 16 + (j >> 1) * 8 + 2 * (lane & 3);
            float w0 = src[col_k * H + row_n];
            float w1 = src[(col_k + 1) * H + row_n];
            __nv_bfloat16 h0 = __float2bfloat16(w0), h1 = __float2bfloat16(w1);
            if (plane == 0) {
                r[j] = (uint32_t)__bfloat16_as_ushort(h0)
                     | ((uint32_t)__bfloat16_as_ushort(h1) << 16);
            } else {
                float l0 = w0 - __bfloat162float(h0);
                float l1 = w1 - __bfloat162float(h1);
                r[j] = (uint32_t)__bfloat16_as_ushort(__float2bfloat16(l0))
                     | ((uint32_t)__bfloat16_as_ushort(__float2bfloat16(l1)) << 16);
            }
        }
        dst[idx] = make_uint4(r[0], r[1], r[2], r[3]);
    }
}

// ---------------- batched chain build ----------------
__global__ void __launch_bounds__(256) build_chain_batched(CBatch bat, int total)
{
    int g = blockIdx.x * blockDim.x + threadIdx.x;
    if (g >= total) return;
    int jb = 0;
    while (jb + 1 < bat.nj && g >= bat.j[jb + 1].ebase) jb++;
    const CJob& J = bat.j[jb];
    int e = g - J.ebase;
    J.next[e] = atomicExch(J.head + __ldg(J.dstI + e), e);
}

// ---------------- batched chain gather (R8-proven: 1 chain / warp) ----------------
__global__ void __launch_bounds__(256) gather_batched(SBatch bat, int total)
{
    int gw = blockIdx.x * (blockDim.x >> 5) + (threadIdx.x >> 5);
    if (gw >= total) return;
    int jb = 0;
    while (jb + 1 < bat.nj && gw >= bat.j[jb + 1].node_base) jb++;
    const SJob& J = bat.j[jb];
    const int node = gw - J.node_base;
    const int lane = threadIdx.x & 31;
    const int doRelu = J.flags & 1;
    const float* x = J.x;
    const int* srcI = J.srcI;
    const int* next = J.next;

    int e = __ldg(J.head + node);
    float4 acc = make_float4(0.f, 0.f, 0.f, 0.f);
    float cnt = 0.f;
    while (e >= 0) {
        int s  = __ldg(srcI + e);
        int nx = __ldg(next + e);
        float4 v = __ldg(((const float4*)(x + (size_t)s * H)) + lane);
        if (doRelu) {
            v.x = fmaxf(v.x, 0.f); v.y = fmaxf(v.y, 0.f);
            v.z = fmaxf(v.z, 0.f); v.w = fmaxf(v.w, 0.f);
        }
        acc.x += v.x; acc.y += v.y; acc.z += v.z; acc.w += v.w;
        cnt += 1.f;
        e = nx;
    }
    float sc = 1.0f / fmaxf(cnt, 1.0f);
    acc.x *= sc; acc.y *= sc; acc.z *= sc; acc.w *= sc;

    if (J.flags & 4) {
        float v[4] = {acc.x, acc.y, acc.z, acc.w};
        uint32_t h[2], l[2];
        #pragma unroll
        for (int p = 0; p < 2; p++) {
            float a = v[2*p], b = v[2*p+1];
            __nv_bfloat16 ah = __float2bfloat16(a), bh = __float2bfloat16(b);
            float ar = a - __bfloat162float(ah), br = b - __bfloat162float(bh);
            h[p] = (uint32_t)__bfloat16_as_ushort(ah) | ((uint32_t)__bfloat16_as_ushort(bh) << 16);
            l[p] = (uint32_t)__bfloat16_as_ushort(__float2bfloat16(ar))
                 | ((uint32_t)__bfloat16_as_ushort(__float2bfloat16(br)) << 16);
        }
        __nv_bfloat16* hi = (__nv_bfloat16*)J.out;
        *(uint2*)(hi + (size_t)node * H + lane * 4) = make_uint2(h[0], h[1]);
        *(uint2*)(hi + (size_t)J.n * H + (size_t)node * H + lane * 4) = make_uint2(l[0], l[1]);
    } else if (J.flags & 2) {
        float* p = J.out + (size_t)node * H + lane * 4;
        asm volatile("red.global.add.v4.f32 [%0], {%1,%2,%3,%4};"
                     :: "l"(p), "f"(acc.x), "f"(acc.y), "f"(acc.z), "f"(acc.w) : "memory");
    } else {
        *(float4*)(J.out + (size_t)node * H + lane * 4) = acc;
    }
}

// ---------------- final linear ----------------
__global__ void __launch_bounds__(128) final_kernel(
    const float* __restrict__ X, const float* __restrict__ W,
    const float* __restrict__ b, float* __restrict__ out, int M)
{
    __shared__ float Ws[H * 64];
    __shared__ float bs[64];
    for (int i = threadIdx.x; i < H * 64; i += 128) Ws[i] = W[i];
    if (threadIdx.x < 64) bs[threadIdx.x] = b[threadIdx.x];
    __syncthreads();
    int m = blockIdx.x * 128 + threadIdx.x;
    if (m >= M) return;
    float acc[64];
    #pragma unroll
    for (int j = 0; j < 64; j++) acc[j] = bs[j];
    const float* x = X + (size_t)m * H;
    for (int k = 0; k < H; k++) {
        float xv = fmaxf(x[k], 0.f);
        #pragma unroll
        for (int j = 0; j < 64; j++) acc[j] += xv * Ws[k * 64 + j];
    }
    float* o = out + (size_t)m * 64;
    #pragma unroll
    for (int j = 0; j < 64; j++) o[j] = acc[j];
}

// ---------------- host ----------------
static const int NN[NTYPE]   = {50000,2000,80000,10000,2000,150000,120000,100000,60000,40000};
static const int OFFS[NTYPE] = {0,50000,52000,132000,142000,144000,294000,414000,514000,574000};
static const int R_SRC[NREL] = {0,1,0,2,0,3,0,4,0,5,0,6,6,7,5,6,5,7,4,5,4,3,2,8,2,9};
static const int R_DST[NREL] = {1,0,2,0,3,0,4,0,5,0,6,0,7,6,6,5,7,5,5,4,3,4,8,2,9,2};
static const int R_EI[NREL]  = {10,10,11,11,12,12,13,13,14,14,15,15,16,16,17,17,18,18,19,19,20,20,21,21,22,22};
static const int R_FLIP[NREL]= {0,1,0,1,0,1,0,1,0,1,0,1,0,1,0,1,0,1,0,1,0,1,0,1,0,1};

static inline int l1_type_needed(int t) { return t < 7; }
static inline int l1_rel_needed(int r)  { return R_DST[r] < 7; }
static inline int l2_rel_needed(int r)  { return R_DST[r] == 0; }

// one-time stream/event setup (host-side only; no device memory)
static cudaStream_t g_s1 = nullptr;
static cudaEvent_t g_evF = nullptr, g_evJ = nullptr;

extern "C" void kernel_launch(void* const* d_in, const int* in_sizes, int n_in,
                              void* d_out, int out_size)
{
    if (!g_s1) {
        cudaStreamCreate(&g_s1);
        cudaEventCreateWithFlags(&g_evF, cudaEventDisableTiming);
        cudaEventCreateWithFlags(&g_evJ, cudaEventDisableTiming);
    }

    const float* Wl   = (const float*)d_in[23];
    const float* bl   = (const float*)d_in[24];
    const float* Wr   = (const float*)d_in[25];
    const float* linW = (const float*)d_in[26];
    const float* linb = (const float*)d_in[27];

    float *buf0, *buf1, *agg, *tmp, *wsum, *bsum;
    int *head, *nxt;
    __nv_bfloat16* wbf;
    cudaGetSymbolAddress((void**)&buf0, g_buf0);
    cudaGetSymbolAddress((void**)&buf1, g_buf1);
    cudaGetSymbolAddress((void**)&agg,  g_agg);
    cudaGetSymbolAddress((void**)&tmp,  g_tmp);
    cudaGetSymbolAddress((void**)&head, g_head);
    cudaGetSymbolAddress((void**)&nxt,  g_next);
    cudaGetSymbolAddress((void**)&wsum, g_wsum);
    cudaGetSymbolAddress((void**)&bsum, g_bsum);
    cudaGetSymbolAddress((void**)&wbf,  g_wbf);

    cudaFuncSetAttribute(gemm_batched, cudaFuncAttributeMaxDynamicSharedMemorySize, SM_BYTES);

    int DEGOFF[NREL], EOFF[NREL];
    {
        int a = 0, b2 = 0;
        for (int r = 0; r < NREL; r++) {
            DEGOFF[r] = a; a += NN[R_DST[r]];
            EOFF[r] = b2; b2 += in_sizes[R_EI[r]] / 2;
        }
    }

    // ---- prep: fork — weights on s0, chains on s1 ----
    cudaEventRecord(g_evF, 0);
    cudaStreamWaitEvent(g_s1, g_evF, 0);

    wsum_kernel<<<2 * NTYPE, 256>>>(Wr, bl, wsum, bsum);
    wcvt_kernel<<<72, 256>>>(wsum, Wl, wbf);

    cudaMemsetAsync(head, 0xFF, (size_t)DEG_TOTAL * sizeof(int), g_s1);
    {
        CBatch cb; cb.nj = 0;
        int etot = 0;
        for (int r = 0; r < NREL; r++) {
            if (!l1_rel_needed(r) && !l2_rel_needed(r)) continue;
            int ii = R_EI[r];
            const int* ei = (const int*)d_in[ii];
            int E = in_sizes[ii] / 2;
            const int* dstI = R_FLIP[r] ? ei : ei + E;
            CJob& J = cb.j[cb.nj++];
            J.dstI = dstI; J.head = head + DEGOFF[r]; J.next = nxt + EOFF[r];
            J.E = E; J.ebase = etot;
            etot += E;
        }
        build_chain_batched<<<(etot + 255) / 256, 256, 0, g_s1>>>(cb, etot);
    }
    cudaEventRecord(g_evJ, g_s1);
    cudaStreamWaitEvent(0, g_evJ, 0);

    const float* cur[NTYPE];
    for (int t = 0; t < NTYPE; t++) cur[t] = (const float*)d_in[t];
    float* bufs[2] = {buf0, buf1};

    for (int layer = 0; layer < 2; layer++) {
        float* outbuf = bufs[layer];
        const int lrelu = (layer == 1);
        const int aflags = lrelu ? 2 : 0;

        GBatch ga; ga.nj = 0; int gaTiles = 0;   // phase A GEMMs (s0)
        SBatch sd; sd.nj = 0; int sdNodes = 0;   // phase A gathers (s1): dst-side presplit
        GBatch gb; gb.nj = 0; int gbTiles = 0;   // phase B GEMMs (s0)
        SBatch ss; ss.nj = 0; int ssNodes = 0;   // phase B gathers (s1): src-side red
        size_t tmpoff = 0, aggoff = 0;

        // self terms -> phase A
        for (int t = 0; t < NTYPE; t++) {
            if (layer == 0 ? !l1_type_needed(t) : (t != 0)) continue;
            int outoff = (layer == 0) ? OFFS[t] : 0;
            GJob& J = ga.j[ga.nj++];
            J.A = cur[t];
            J.Wb = wbf + (size_t)(layer * NTYPE + t) * 2 * H * H;
            J.bias = bsum + ((size_t)layer * NTYPE + t) * H;
            J.C = outbuf + (size_t)outoff * H;
            J.M = NN[t]; J.tile_base = gaTiles; J.flags = aflags;
            gaTiles += (NN[t] + 63) / 64;
        }

        // neighbor terms
        for (int r = 0; r < NREL; r++) {
            if (layer == 0 ? !l1_rel_needed(r) : !l2_rel_needed(r)) continue;
            int s = R_SRC[r], d = R_DST[r], ii = R_EI[r];
            const int* ei = (const int*)d_in[ii];
            int E = in_sizes[ii] / 2;
            const int* srcI = R_FLIP[r] ? ei + E : ei;
            int nd = NN[d];
            int outoff = (layer == 0) ? OFFS[d] : 0;
            const __nv_bfloat16* wmat = wbf + (size_t)(20 + layer * NREL + r) * 2 * H * H;

            // overlap-aware side choice: src-side only when it shrinks the GEMM by >1.4x
            if ((long)NN[s] * 7 < (long)nd * 5) {
                // src-side: GEMM into tmp (phase A, s0), gather-red into out (phase B, s1)
                float* tp = tmp + tmpoff * H;
                tmpoff += NN[s];
                GJob& J = ga.j[ga.nj++];
                J.A = cur[s]; J.Wb = wmat; J.bias = nullptr; J.C = tp;
                J.M = NN[s]; J.tile_base = gaTiles; J.flags = aflags;
                gaTiles += (NN[s] + 63) / 64;

                SJob& S = ss.j[ss.nj++];
                S.x = tp; S.srcI = srcI; S.head = head + DEGOFF[r]; S.next = nxt + EOFF[r];
                S.out = outbuf + (size_t)outoff * H; S.n = nd;
                S.node_base = ssNodes; S.flags = 2;
                ssNodes += nd;
            } else {
                // dst-side: gather mean -> presplit planes (phase A, s1), GEMM-red (phase B, s0)
                float* ap = agg + aggoff * H;
                aggoff += nd;
                SJob& S = sd.j[sd.nj++];
                S.x = cur[s]; S.srcI = srcI; S.head = head + DEGOFF[r]; S.next = nxt + EOFF[r];
                S.out = ap; S.n = nd;
                S.node_base = sdNodes; S.flags = (lrelu ? 1 : 0) | 4;
                sdNodes += nd;

                GJob& J = gb.j[gb.nj++];
                J.A = ap; J.Wb = wmat; J.bias = nullptr;
                J.C = outbuf + (size_t)outoff * H;
                J.M = nd; J.tile_base = gbTiles; J.flags = 1 | 4;
                gbTiles += (nd + 63) / 64;
            }
        }

        // ---- Phase A: ga (s0) || sd (s1) ----
        cudaEventRecord(g_evF, 0);
        cudaStreamWaitEvent(g_s1, g_evF, 0);
        gemm_batched<<<gaTiles, 128, SM_BYTES>>>(ga);
        gather_batched<<<(sdNodes + 7) / 8, 256, 0, g_s1>>>(sd, sdNodes);
        cudaEventRecord(g_evJ, g_s1);
        cudaStreamWaitEvent(0, g_evJ, 0);

        // ---- Phase B: gb (s0) || ss (s1) ----
        cudaEventRecord(g_evF, 0);
        cudaStreamWaitEvent(g_s1, g_evF, 0);
        gemm_batched<<<gbTiles, 128, SM_BYTES>>>(gb);
        gather_batched<<<(ssNodes + 7) / 8, 256, 0, g_s1>>>(ss, ssNodes);
        cudaEventRecord(g_evJ, g_s1);
        cudaStreamWaitEvent(0, g_evJ, 0);

        if (layer == 0)
            for (int t = 0; t < 7; t++) cur[t] = buf0 + (size_t)OFFS[t] * H;
    }

    final_kernel<<<(BUF1_ROWS + 127) / 128, 128>>>(buf1, linW, linb, (float*)d_out, BUF1_ROWS);
}

// round 17
// speedup vs baseline: 1.1070x; 1.0684x over previous
#include <cuda_runtime.h>
#include <cuda_bf16.h>
#include <cstdint>
#include <cstddef>

#define H 128
#define NTYPE 10
#define NREL 26
#define DEG_TOTAL 1828000
#define EDGE_TOTAL (26 * 300000)
#define BUF0_ROWS 414000
#define BUF1_ROWS 50000
#define TMP_ROWS 600000
#define AGG_ROWS 700000
#define SCAN_NBLK ((DEG_TOTAL + 2047) / 2048)

// ---------------- scratch ----------------
__device__ float g_buf0[(size_t)BUF0_ROWS * H];
__device__ float g_buf1[(size_t)BUF1_ROWS * H];
__device__ float g_agg[(size_t)AGG_ROWS * H];
__device__ float g_tmp[(size_t)TMP_ROWS * H];
__device__ int   g_deg[DEG_TOTAL];          // degree counts
__device__ int   g_rowptr[DEG_TOTAL + 1];   // CSR row pointers (concatenated node space)
__device__ int   g_cursor[DEG_TOTAL];       // fill cursors
__device__ int   g_csrc[EDGE_TOTAL];        // CSR source-index array
__device__ int   g_bsums[1024];
__device__ float g_wsum[2 * NTYPE * H * H];
__device__ float g_bsum[2 * NTYPE * H];
__device__ __nv_bfloat16 g_wbf[72 * 2 * H * H];

__constant__ int c_rel_dst[NREL] = {1,0,2,0,3,0,4,0,5,0,6,0,7,6,6,5,7,5,5,4,3,4,8,2,9,2};

// ---------------- job descriptors ----------------
struct GJob { const float* A; const __nv_bfloat16* Wb; const float* bias; float* C;
              int M; int tile_base; int flags; int _pad; };
struct GBatch { GJob j[20]; int nj; };

// SJob: head = rowptr + DEGOFF[r]; next = csrc (global)
struct SJob { const float* x; const int* srcI; const int* head; const int* next;
              float* out; int n; int node_base; int flags; };
struct SBatch { SJob j[14]; int nj; };

struct CJob { const int* dstI; int* head; int* next; int E; int ebase; int _pad; };
struct CBatch { CJob j[22]; int nj; };

// ---------------- helpers ----------------
__device__ __forceinline__ uint32_t smem_to_u32(const void* p) {
    uint32_t a;
    asm("{ .reg .u64 t; cvta.to.shared.u64 t, %1; cvt.u32.u64 %0, t; }" : "=r"(a) : "l"(p));
    return a;
}

__device__ __forceinline__ void cvt8(const float* v, uint4& hi, uint4& lo) {
    uint32_t h[4], l[4];
    #pragma unroll
    for (int p = 0; p < 4; p++) {
        float a = v[2*p], b = v[2*p+1];
        __nv_bfloat16 ah = __float2bfloat16(a), bh = __float2bfloat16(b);
        float ar = a - __bfloat162float(ah), br = b - __bfloat162float(bh);
        __nv_bfloat16 al = __float2bfloat16(ar), bl2 = __float2bfloat16(br);
        h[p] = (uint32_t)__bfloat16_as_ushort(ah) | ((uint32_t)__bfloat16_as_ushort(bh) << 16);
        l[p] = (uint32_t)__bfloat16_as_ushort(al) | ((uint32_t)__bfloat16_as_ushort(bl2) << 16);
    }
    hi = make_uint4(h[0], h[1], h[2], h[3]);
    lo = make_uint4(l[0], l[1], l[2], l[3]);
}

#define LDMATRIX_X4(r0, r1, r2, r3, addr) \
    asm volatile("ldmatrix.sync.aligned.m8n8.x4.shared.b16 {%0,%1,%2,%3}, [%4];" \
                 : "=r"(r0), "=r"(r1), "=r"(r2), "=r"(r3) : "r"(addr))

#define MMA_BF16(c0, c1, c2, c3, a0, a1, a2, a3, b0, b1) \
    asm volatile("mma.sync.aligned.m16n8k16.row.col.f32.bf16.bf16.f32 " \
                 "{%0,%1,%2,%3}, {%4,%5,%6,%7}, {%8,%9}, {%0,%1,%2,%3};" \
                 : "+f"(c0), "+f"(c1), "+f"(c2), "+f"(c3) \
                 : "r"(a0), "r"(a1), "r"(a2), "r"(a3), "r"(b0), "r"(b1))

// ---------------- batched bf16 HMMA GEMM: 64x128 tile, 128 thr (4 warps, 32x64/warp) --
#define A_LD 136
#define SM_AH 0
#define SM_AL 17408
#define SM_BYTES 34816

__global__ void __launch_bounds__(128, 4) gemm_batched(GBatch bat)
{
    extern __shared__ char smem[];
    const uint32_t sb = smem_to_u32(smem);
    const int tid = threadIdx.x, lane = tid & 31, wid = tid >> 5;

    int jb = 0;
    while (jb + 1 < bat.nj && (int)blockIdx.x >= bat.j[jb + 1].tile_base) jb++;
    const GJob& J = bat.j[jb];
    const int m0 = (blockIdx.x - J.tile_base) * 64;
    const int M = J.M;
    const int accumulate = J.flags & 1;
    const int doRelu = J.flags & 2;
    const int presplit = J.flags & 4;
    const float* bias = J.bias;
    float* C = J.C;

    // ---- stage A (64 rows) ----
    if (presplit) {
        const uint4* srcH = (const uint4*)J.A + (size_t)m0 * 16;
        const uint4* srcL = (const uint4*)((const __nv_bfloat16*)J.A + (size_t)M * H) + (size_t)m0 * 16;
        #pragma unroll
        for (int it = 0; it < 8; it++) {
            int idx = tid + it * 128;
            int n = idx >> 4, q = idx & 15;
            *(uint4*)(smem + SM_AH + (size_t)n * (A_LD * 2) + q * 16) = srcH[idx];
            *(uint4*)(smem + SM_AL + (size_t)n * (A_LD * 2) + q * 16) = srcL[idx];
        }
    } else {
        const int r = tid >> 1;
        const int co = (tid & 1) * 64;
        const int m = m0 + r;
        if (m < M) {
            const float4* Ar = (const float4*)(J.A + (size_t)m * H);
            #pragma unroll
            for (int c = 0; c < 64; c += 8) {
                float4 f0 = Ar[(co + c) >> 2], f1 = Ar[((co + c) >> 2) + 1];
                float v[8] = {f0.x,f0.y,f0.z,f0.w,f1.x,f1.y,f1.z,f1.w};
                if (doRelu) {
                    #pragma unroll
                    for (int j = 0; j < 8; j++) v[j] = fmaxf(v[j], 0.f);
                }
                uint4 hi, lo;
                cvt8(v, hi, lo);
                *(uint4*)(smem + SM_AH + (size_t)(r * A_LD + co + c) * 2) = hi;
                *(uint4*)(smem + SM_AL + (size_t)(r * A_LD + co + c) * 2) = lo;
            }
        } else {
            uint4 z = make_uint4(0,0,0,0);
            #pragma unroll
            for (int c = 0; c < 64; c += 8) {
                *(uint4*)(smem + SM_AH + (size_t)(r * A_LD + co + c) * 2) = z;
                *(uint4*)(smem + SM_AL + (size_t)(r * A_LD + co + c) * 2) = z;
            }
        }
    }
    __syncthreads();

    const int warp_m = (wid >> 1) * 32;
    const int warp_n = (wid & 1) * 64;
    const int npg = warp_n >> 4;

    float acc[2][8][4];
    #pragma unroll
    for (int mt = 0; mt < 2; mt++)
        #pragma unroll
        for (int nt = 0; nt < 8; nt++)
            #pragma unroll
            for (int q = 0; q < 4; q++) acc[mt][nt][q] = 0.0f;

    const int lrow = lane & 15;
    const int lcol = (lane >> 4) << 3;

    uint32_t aoff[2];
    #pragma unroll
    for (int mt = 0; mt < 2; mt++)
        aoff[mt] = (uint32_t)(((warp_m + mt * 16 + lrow) * A_LD + lcol) * 2);

    const uint4* __restrict__ WbF = (const uint4*)J.Wb;

    #pragma unroll
    for (int ks = 0; ks < 8; ks++) {
        const uint32_t kb = ks * 32;
        uint4 bh[4], bl[4];
        #pragma unroll
        for (int np = 0; np < 4; np++) {
            bh[np] = __ldg(WbF + (((0 + npg + np) * 8 + ks) * 32 + lane));
            bl[np] = __ldg(WbF + (((8 + npg + np) * 8 + ks) * 32 + lane));
        }
        uint32_t ah[2][4], al[2][4];
        #pragma unroll
        for (int mt = 0; mt < 2; mt++) {
            LDMATRIX_X4(ah[mt][0], ah[mt][1], ah[mt][2], ah[mt][3], sb + SM_AH + aoff[mt] + kb);
            LDMATRIX_X4(al[mt][0], al[mt][1], al[mt][2], al[mt][3], sb + SM_AL + aoff[mt] + kb);
        }
        #pragma unroll
        for (int mt = 0; mt < 2; mt++) {
            #pragma unroll
            for (int np = 0; np < 4; np++) {
                const int n0 = np * 2, n1 = np * 2 + 1;
                MMA_BF16(acc[mt][n0][0], acc[mt][n0][1], acc[mt][n0][2], acc[mt][n0][3],
                         ah[mt][0], ah[mt][1], ah[mt][2], ah[mt][3], bh[np].x, bh[np].z);
                MMA_BF16(acc[mt][n1][0], acc[mt][n1][1], acc[mt][n1][2], acc[mt][n1][3],
                         ah[mt][0], ah[mt][1], ah[mt][2], ah[mt][3], bh[np].y, bh[np].w);
                MMA_BF16(acc[mt][n0][0], acc[mt][n0][1], acc[mt][n0][2], acc[mt][n0][3],
                         al[mt][0], al[mt][1], al[mt][2], al[mt][3], bh[np].x, bh[np].z);
                MMA_BF16(acc[mt][n1][0], acc[mt][n1][1], acc[mt][n1][2], acc[mt][n1][3],
                         al[mt][0], al[mt][1], al[mt][2], al[mt][3], bh[np].y, bh[np].w);
                MMA_BF16(acc[mt][n0][0], acc[mt][n0][1], acc[mt][n0][2], acc[mt][n0][3],
                         ah[mt][0], ah[mt][1], ah[mt][2], ah[mt][3], bl[np].x, bl[np].z);
                MMA_BF16(acc[mt][n1][0], acc[mt][n1][1], acc[mt][n1][2], acc[mt][n1][3],
                         ah[mt][0], ah[mt][1], ah[mt][2], ah[mt][3], bl[np].y, bl[np].w);
            }
        }
    }

    const int qrow = lane >> 2;
    const int qcol = (lane & 3) * 2;
    #pragma unroll
    for (int mt = 0; mt < 2; mt++) {
        #pragma unroll
        for (int half = 0; half < 2; half++) {
            const int m = m0 + warp_m + mt * 16 + qrow + half * 8;
            if (m < M) {
                float* cp = C + (size_t)m * H;
                #pragma unroll
                for (int nt = 0; nt < 8; nt++) {
                    const int c = warp_n + nt * 8 + qcol;
                    float v0 = acc[mt][nt][half * 2 + 0];
                    float v1 = acc[mt][nt][half * 2 + 1];
                    if (accumulate) {
                        asm volatile("red.global.add.v2.f32 [%0], {%1,%2};"
                                     :: "l"(cp + c), "f"(v0), "f"(v1) : "memory");
                    } else {
                        if (bias) { v0 += bias[c]; v1 += bias[c + 1]; }
                        *(float2*)(cp + c) = make_float2(v0, v1);
                    }
                }
            }
        }
    }
}

// ---------------- Wr / bias reduction ----------------
__global__ void __launch_bounds__(256) wsum_kernel(
    const float* __restrict__ Wr, const float* __restrict__ bl,
    float* __restrict__ wsum, float* __restrict__ bsum)
{
    int layer = blockIdx.x / NTYPE;
    int t = blockIdx.x % NTYPE;
    const float* base = Wr + (size_t)layer * NREL * H * H;
    float* outw = wsum + ((size_t)layer * NTYPE + t) * H * H;
    for (int e = threadIdx.x; e < H * H; e += 256) {
        float a = 0.f;
        #pragma unroll
        for (int r = 0; r < NREL; r++)
            if (c_rel_dst[r] == t) a += base[(size_t)r * H * H + e];
        outw[e] = a;
    }
    if (threadIdx.x < H) {
        float a = 0.f;
        #pragma unroll
        for (int r = 0; r < NREL; r++)
            if (c_rel_dst[r] == t) a += bl[((size_t)layer * NREL + r) * H + threadIdx.x];
        bsum[((size_t)layer * NTYPE + t) * H + threadIdx.x] = a;
    }
}

// ---------------- weight conversion ----------------
__global__ void __launch_bounds__(256) wcvt_kernel(
    const float* __restrict__ wsum, const float* __restrict__ Wl,
    __nv_bfloat16* __restrict__ wbf)
{
    int m = blockIdx.x;
    const float* src = (m < 20) ? (wsum + (size_t)m * H * H)
                                : (Wl + (size_t)(m - 20) * H * H);
    uint4* dst = (uint4*)(wbf + (size_t)m * 2 * H * H);
    for (int idx = threadIdx.x; idx < 4096; idx += 256) {
        int plane = idx >> 11;
        int npg = (idx >> 8) & 7;
        int ks = (idx >> 5) & 7;
        int lane = idx & 31;
        uint32_t r[4];
        #pragma unroll
        for (int j = 0; j < 4; j++) {
            int row_n = npg * 16 + (j & 1) * 8 + (lane >> 2);
            int col_k = ks * 16 + (j >> 1) * 8 + 2 * (lane & 3);
            float w0 = src[col_k * H + row_n];
            float w1 = src[(col_k + 1) * H + row_n];
            __nv_bfloat16 h0 = __float2bfloat16(w0), h1 = __float2bfloat16(w1);
            if (plane == 0) {
                r[j] = (uint32_t)__bfloat16_as_ushort(h0)
                     | ((uint32_t)__bfloat16_as_ushort(h1) << 16);
            } else {
                float l0 = w0 - __bfloat162float(h0);
                float l1 = w1 - __bfloat162float(h1);
                r[j] = (uint32_t)__bfloat16_as_ushort(__float2bfloat16(l0))
                     | ((uint32_t)__bfloat16_as_ushort(__float2bfloat16(l1)) << 16);
            }
        }
        dst[idx] = make_uint4(r[0], r[1], r[2], r[3]);
    }
}

// ---------------- CSR build: count, scan(3), fill ----------------
__global__ void __launch_bounds__(256) deg_count_batched(CBatch bat, int total)
{
    int g = blockIdx.x * blockDim.x + threadIdx.x;
    if (g >= total) return;
    int jb = 0;
    while (jb + 1 < bat.nj && g >= bat.j[jb + 1].ebase) jb++;
    const CJob& J = bat.j[jb];
    atomicAdd(J.head + __ldg(J.dstI + (g - J.ebase)), 1);
}

__global__ void __launch_bounds__(256) scan_part(const int* __restrict__ deg, int* __restrict__ bsums)
{
    __shared__ int tsum[256];
    const int tid = threadIdx.x;
    int base = blockIdx.x * 2048 + tid * 8;
    int s = 0;
    #pragma unroll
    for (int j = 0; j < 8; j++) { int idx = base + j; if (idx < DEG_TOTAL) s += deg[idx]; }
    tsum[tid] = s; __syncthreads();
    for (int off = 128; off > 0; off >>= 1) {
        if (tid < off) tsum[tid] += tsum[tid + off];
        __syncthreads();
    }
    if (tid == 0) bsums[blockIdx.x] = tsum[0];
}

__global__ void __launch_bounds__(1024) scan_sums(int* __restrict__ bsums, int nb, int* __restrict__ rowptr)
{
    __shared__ int sh[1024];
    const int tid = threadIdx.x;
    int v = (tid < nb) ? bsums[tid] : 0;
    sh[tid] = v; __syncthreads();
    for (int off = 1; off < 1024; off <<= 1) {
        int t = 0;
        if (tid >= off) t = sh[tid - off];
        __syncthreads();
        sh[tid] += t;
        __syncthreads();
    }
    if (tid < nb) bsums[tid] = sh[tid] - v;
    if (tid == 1023) rowptr[DEG_TOTAL] = sh[1023];
}

__global__ void __launch_bounds__(256) scan_final(
    const int* __restrict__ deg, const int* __restrict__ bsums,
    int* __restrict__ rowptr, int* __restrict__ cursor)
{
    __shared__ int tsum[256];
    const int tid = threadIdx.x;
    int base = blockIdx.x * 2048 + tid * 8;
    int loc[8]; int s = 0;
    #pragma unroll
    for (int j = 0; j < 8; j++) { loc[j] = s; int idx = base + j; if (idx < DEG_TOTAL) s += deg[idx]; }
    tsum[tid] = s; __syncthreads();
    for (int off = 1; off < 256; off <<= 1) {
        int t = 0;
        if (tid >= off) t = tsum[tid - off];
        __syncthreads();
        tsum[tid] += t;
        __syncthreads();
    }
    int boff = bsums[blockIdx.x] + tsum[tid] - s;
    #pragma unroll
    for (int j = 0; j < 8; j++) {
        int idx = base + j;
        if (idx < DEG_TOTAL) { rowptr[idx] = boff + loc[j]; cursor[idx] = boff + loc[j]; }
    }
}

__global__ void __launch_bounds__(256) csr_fill_batched(CBatch bat, int* __restrict__ csrc, int total)
{
    int g = blockIdx.x * blockDim.x + threadIdx.x;
    if (g >= total) return;
    int jb = 0;
    while (jb + 1 < bat.nj && g >= bat.j[jb + 1].ebase) jb++;
    const CJob& J = bat.j[jb];
    int e = g - J.ebase;
    int d = __ldg(J.dstI + e);
    int pos = atomicAdd(J.head + d, 1);
    csrc[pos] = __ldg(J.next + e);
}

// ---------------- batched CSR gather: 1 node per warp, no pointer chase --------------
__global__ void __launch_bounds__(256) gather_batched(SBatch bat, int total)
{
    int gw = blockIdx.x * (blockDim.x >> 5) + (threadIdx.x >> 5);
    if (gw >= total) return;
    int jb = 0;
    while (jb + 1 < bat.nj && gw >= bat.j[jb + 1].node_base) jb++;
    const SJob& J = bat.j[jb];
    const int node = gw - J.node_base;
    const int lane = threadIdx.x & 31;
    const int doRelu = J.flags & 1;
    const float* x = J.x;
    const int* csrc = J.next;

    int b = __ldg(J.head + node);
    int eEnd = __ldg(J.head + node + 1);
    float cnt = (float)(eEnd - b);
    float4 acc = make_float4(0.f, 0.f, 0.f, 0.f);

    int e = b;
    for (; e + 2 <= eEnd; e += 2) {
        int s0 = __ldg(csrc + e);
        int s1 = __ldg(csrc + e + 1);
        float4 v0 = __ldg(((const float4*)(x + (size_t)s0 * H)) + lane);
        float4 v1 = __ldg(((const float4*)(x + (size_t)s1 * H)) + lane);
        if (doRelu) {
            v0.x = fmaxf(v0.x, 0.f); v0.y = fmaxf(v0.y, 0.f);
            v0.z = fmaxf(v0.z, 0.f); v0.w = fmaxf(v0.w, 0.f);
            v1.x = fmaxf(v1.x, 0.f); v1.y = fmaxf(v1.y, 0.f);
            v1.z = fmaxf(v1.z, 0.f); v1.w = fmaxf(v1.w, 0.f);
        }
        acc.x += v0.x + v1.x; acc.y += v0.y + v1.y;
        acc.z += v0.z + v1.z; acc.w += v0.w + v1.w;
    }
    if (e < eEnd) {
        int s0 = __ldg(csrc + e);
        float4 v0 = __ldg(((const float4*)(x + (size_t)s0 * H)) + lane);
        if (doRelu) {
            v0.x = fmaxf(v0.x, 0.f); v0.y = fmaxf(v0.y, 0.f);
            v0.z = fmaxf(v0.z, 0.f); v0.w = fmaxf(v0.w, 0.f);
        }
        acc.x += v0.x; acc.y += v0.y; acc.z += v0.z; acc.w += v0.w;
    }

    float sc = 1.0f / fmaxf(cnt, 1.0f);
    acc.x *= sc; acc.y *= sc; acc.z *= sc; acc.w *= sc;

    if (J.flags & 4) {
        float v[4] = {acc.x, acc.y, acc.z, acc.w};
        uint32_t h[2], l[2];
        #pragma unroll
        for (int p = 0; p < 2; p++) {
            float a = v[2*p], b2 = v[2*p+1];
            __nv_bfloat16 ah = __float2bfloat16(a), bh = __float2bfloat16(b2);
            float ar = a - __bfloat162float(ah), br = b2 - __bfloat162float(bh);
            h[p] = (uint32_t)__bfloat16_as_ushort(ah) | ((uint32_t)__bfloat16_as_ushort(bh) << 16);
            l[p] = (uint32_t)__bfloat16_as_ushort(__float2bfloat16(ar))
                 | ((uint32_t)__bfloat16_as_ushort(__float2bfloat16(br)) << 16);
        }
        __nv_bfloat16* hi = (__nv_bfloat16*)J.out;
        *(uint2*)(hi + (size_t)node * H + lane * 4) = make_uint2(h[0], h[1]);
        *(uint2*)(hi + (size_t)J.n * H + (size_t)node * H + lane * 4) = make_uint2(l[0], l[1]);
    } else if (J.flags & 2) {
        float* p = J.out + (size_t)node * H + lane * 4;
        asm volatile("red.global.add.v4.f32 [%0], {%1,%2,%3,%4};"
                     :: "l"(p), "f"(acc.x), "f"(acc.y), "f"(acc.z), "f"(acc.w) : "memory");
    } else {
        *(float4*)(J.out + (size_t)node * H + lane * 4) = acc;
    }
}

// ---------------- final linear ----------------
__global__ void __launch_bounds__(128) final_kernel(
    const float* __restrict__ X, const float* __restrict__ W,
    const float* __restrict__ b, float* __restrict__ out, int M)
{
    __shared__ float Ws[H * 64];
    __shared__ float bs[64];
    for (int i = threadIdx.x; i < H * 64; i += 128) Ws[i] = W[i];
    if (threadIdx.x < 64) bs[threadIdx.x] = b[threadIdx.x];
    __syncthreads();
    int m = blockIdx.x * 128 + threadIdx.x;
    if (m >= M) return;
    float acc[64];
    #pragma unroll
    for (int j = 0; j < 64; j++) acc[j] = bs[j];
    const float* x = X + (size_t)m * H;
    for (int k = 0; k < H; k++) {
        float xv = fmaxf(x[k], 0.f);
        #pragma unroll
        for (int j = 0; j < 64; j++) acc[j] += xv * Ws[k * 64 + j];
    }
    float* o = out + (size_t)m * 64;
    #pragma unroll
    for (int j = 0; j < 64; j++) o[j] = acc[j];
}

// ---------------- host ----------------
static const int NN[NTYPE]   = {50000,2000,80000,10000,2000,150000,120000,100000,60000,40000};
static const int OFFS[NTYPE] = {0,50000,52000,132000,142000,144000,294000,414000,514000,574000};
static const int R_SRC[NREL] = {0,1,0,2,0,3,0,4,0,5,0,6,6,7,5,6,5,7,4,5,4,3,2,8,2,9};
static const int R_DST[NREL] = {1,0,2,0,3,0,4,0,5,0,6,0,7,6,6,5,7,5,5,4,3,4,8,2,9,2};
static const int R_EI[NREL]  = {10,10,11,11,12,12,13,13,14,14,15,15,16,16,17,17,18,18,19,19,20,20,21,21,22,22};
static const int R_FLIP[NREL]= {0,1,0,1,0,1,0,1,0,1,0,1,0,1,0,1,0,1,0,1,0,1,0,1,0,1};

static inline int l1_type_needed(int t) { return t < 7; }
static inline int l1_rel_needed(int r)  { return R_DST[r] < 7; }
static inline int l2_rel_needed(int r)  { return R_DST[r] == 0; }

static cudaStream_t g_s1 = nullptr;
static cudaEvent_t g_evF = nullptr, g_evJ = nullptr;

extern "C" void kernel_launch(void* const* d_in, const int* in_sizes, int n_in,
                              void* d_out, int out_size)
{
    if (!g_s1) {
        cudaStreamCreate(&g_s1);
        cudaEventCreateWithFlags(&g_evF, cudaEventDisableTiming);
        cudaEventCreateWithFlags(&g_evJ, cudaEventDisableTiming);
    }

    const float* Wl   = (const float*)d_in[23];
    const float* bl   = (const float*)d_in[24];
    const float* Wr   = (const float*)d_in[25];
    const float* linW = (const float*)d_in[26];
    const float* linb = (const float*)d_in[27];

    float *buf0, *buf1, *agg, *tmp, *wsum, *bsum;
    int *deg, *rowptr, *cursor, *csrc, *bsums;
    __nv_bfloat16* wbf;
    cudaGetSymbolAddress((void**)&buf0,   g_buf0);
    cudaGetSymbolAddress((void**)&buf1,   g_buf1);
    cudaGetSymbolAddress((void**)&agg,    g_agg);
    cudaGetSymbolAddress((void**)&tmp,    g_tmp);
    cudaGetSymbolAddress((void**)&deg,    g_deg);
    cudaGetSymbolAddress((void**)&rowptr, g_rowptr);
    cudaGetSymbolAddress((void**)&cursor, g_cursor);
    cudaGetSymbolAddress((void**)&csrc,   g_csrc);
    cudaGetSymbolAddress((void**)&bsums,  g_bsums);
    cudaGetSymbolAddress((void**)&wsum,   g_wsum);
    cudaGetSymbolAddress((void**)&bsum,   g_bsum);
    cudaGetSymbolAddress((void**)&wbf,    g_wbf);

    cudaFuncSetAttribute(gemm_batched, cudaFuncAttributeMaxDynamicSharedMemorySize, SM_BYTES);

    int DEGOFF[NREL];
    {
        int a = 0;
        for (int r = 0; r < NREL; r++) { DEGOFF[r] = a; a += NN[R_DST[r]]; }
    }

    // ---- prep: fork — weights on s0, CSR build on s1 ----
    cudaEventRecord(g_evF, 0);
    cudaStreamWaitEvent(g_s1, g_evF, 0);

    wsum_kernel<<<2 * NTYPE, 256>>>(Wr, bl, wsum, bsum);
    wcvt_kernel<<<72, 256>>>(wsum, Wl, wbf);

    cudaMemsetAsync(deg, 0, (size_t)DEG_TOTAL * sizeof(int), g_s1);
    {
        CBatch cbc, cbf; cbc.nj = 0; cbf.nj = 0;
        int etot = 0;
        for (int r = 0; r < NREL; r++) {
            if (!l1_rel_needed(r) && !l2_rel_needed(r)) continue;
            int ii = R_EI[r];
            const int* ei = (const int*)d_in[ii];
            int E = in_sizes[ii] / 2;
            const int* dstI = R_FLIP[r] ? ei : ei + E;
            const int* srcI = R_FLIP[r] ? ei + E : ei;
            CJob& Jc = cbc.j[cbc.nj++];
            Jc.dstI = dstI; Jc.head = deg + DEGOFF[r]; Jc.next = nullptr;
            Jc.E = E; Jc.ebase = etot;
            CJob& Jf = cbf.j[cbf.nj++];
            Jf.dstI = dstI; Jf.head = cursor + DEGOFF[r]; Jf.next = (int*)srcI;
            Jf.E = E; Jf.ebase = etot;
            etot += E;
        }
        deg_count_batched<<<(etot + 255) / 256, 256, 0, g_s1>>>(cbc, etot);
        scan_part<<<SCAN_NBLK, 256, 0, g_s1>>>(deg, bsums);
        scan_sums<<<1, 1024, 0, g_s1>>>(bsums, SCAN_NBLK, rowptr);
        scan_final<<<SCAN_NBLK, 256, 0, g_s1>>>(deg, bsums, rowptr, cursor);
        csr_fill_batched<<<(etot + 255) / 256, 256, 0, g_s1>>>(cbf, csrc, etot);
    }
    cudaEventRecord(g_evJ, g_s1);
    cudaStreamWaitEvent(0, g_evJ, 0);

    const float* cur[NTYPE];
    for (int t = 0; t < NTYPE; t++) cur[t] = (const float*)d_in[t];
    float* bufs[2] = {buf0, buf1};

    for (int layer = 0; layer < 2; layer++) {
        float* outbuf = bufs[layer];
        const int lrelu = (layer == 1);
        const int aflags = lrelu ? 2 : 0;

        GBatch ga; ga.nj = 0; int gaTiles = 0;
        SBatch sd; sd.nj = 0; int sdNodes = 0;
        GBatch gb; gb.nj = 0; int gbTiles = 0;
        SBatch ss; ss.nj = 0; int ssNodes = 0;
        size_t tmpoff = 0, aggoff = 0;

        // self terms -> phase A
        for (int t = 0; t < NTYPE; t++) {
            if (layer == 0 ? !l1_type_needed(t) : (t != 0)) continue;
            int outoff = (layer == 0) ? OFFS[t] : 0;
            GJob& J = ga.j[ga.nj++];
            J.A = cur[t];
            J.Wb = wbf + (size_t)(layer * NTYPE + t) * 2 * H * H;
            J.bias = bsum + ((size_t)layer * NTYPE + t) * H;
            J.C = outbuf + (size_t)outoff * H;
            J.M = NN[t]; J.tile_base = gaTiles; J.flags = aflags;
            gaTiles += (NN[t] + 63) / 64;
        }

        // neighbor terms
        for (int r = 0; r < NREL; r++) {
            if (layer == 0 ? !l1_rel_needed(r) : !l2_rel_needed(r)) continue;
            int s = R_SRC[r], d = R_DST[r], ii = R_EI[r];
            const int* ei = (const int*)d_in[ii];
            int E = in_sizes[ii] / 2;
            const int* srcI = R_FLIP[r] ? ei + E : ei;
            int nd = NN[d];
            int outoff = (layer == 0) ? OFFS[d] : 0;
            const __nv_bfloat16* wmat = wbf + (size_t)(20 + layer * NREL + r) * 2 * H * H;

            if ((long)NN[s] * 7 < (long)nd * 5) {
                float* tp = tmp + tmpoff * H;
                tmpoff += NN[s];
                GJob& J = ga.j[ga.nj++];
                J.A = cur[s]; J.Wb = wmat; J.bias = nullptr; J.C = tp;
                J.M = NN[s]; J.tile_base = gaTiles; J.flags = aflags;
                gaTiles += (NN[s] + 63) / 64;

                SJob& S = ss.j[ss.nj++];
                S.x = tp; S.srcI = srcI; S.head = rowptr + DEGOFF[r]; S.next = csrc;
                S.out = outbuf + (size_t)outoff * H; S.n = nd;
                S.node_base = ssNodes; S.flags = 2;
                ssNodes += nd;
            } else {
                float* ap = agg + aggoff * H;
                aggoff += nd;
                SJob& S = sd.j[sd.nj++];
                S.x = cur[s]; S.srcI = srcI; S.head = rowptr + DEGOFF[r]; S.next = csrc;
                S.out = ap; S.n = nd;
                S.node_base = sdNodes; S.flags = (lrelu ? 1 : 0) | 4;
                sdNodes += nd;

                GJob& J = gb.j[gb.nj++];
                J.A = ap; J.Wb = wmat; J.bias = nullptr;
                J.C = outbuf + (size_t)outoff * H;
                J.M = nd; J.tile_base = gbTiles; J.flags = 1 | 4;
                gbTiles += (nd + 63) / 64;
            }
        }

        // ---- Phase A: ga (s0) || sd (s1) ----
        cudaEventRecord(g_evF, 0);
        cudaStreamWaitEvent(g_s1, g_evF, 0);
        gemm_batched<<<gaTiles, 128, SM_BYTES>>>(ga);
        gather_batched<<<(sdNodes + 7) / 8, 256, 0, g_s1>>>(sd, sdNodes);
        cudaEventRecord(g_evJ, g_s1);
        cudaStreamWaitEvent(0, g_evJ, 0);

        // ---- Phase B: gb (s0) || ss (s1) ----
        cudaEventRecord(g_evF, 0);
        cudaStreamWaitEvent(g_s1, g_evF, 0);
        gemm_batched<<<gbTiles, 128, SM_BYTES>>>(gb);
        gather_batched<<<(ssNodes + 7) / 8, 256, 0, g_s1>>>(ss, ssNodes);
        cudaEventRecord(g_evJ, g_s1);
        cudaStreamWaitEvent(0, g_evJ, 0);

        if (layer == 0)
            for (int t = 0; t < 7; t++) cur[t] = buf0 + (size_t)OFFS[t] * H;
    }

    final_kernel<<<(BUF1_ROWS + 127) / 128, 128>>>(buf1, linW, linb, (float*)d_out, BUF1_ROWS);
}